// round 17
// baseline (speedup 1.0000x reference)
#include <cuda_runtime.h>
#include <cuda_fp16.h>
#include <math.h>
#include <stdint.h>

#define NB    20
#define BSZ   64
#define DM    768
#define NH    12
#define DI    3072
#define QKV_N (3*DM)          // 2304
#define S_TOK (2*NB*BSZ)      // 2560 tokens per stream
#define S2    (2*S_TOK)       // 5120 both streams

// ---------------- scratch (device globals; no allocation allowed) ----------
__device__ float g_a   [S2 * DM];
__device__ float g_qkv [S2 * QKV_N];
__device__ float g_attm[S2 * DM];
__device__ float g_xa  [S2 * DM];
__device__ float g_h   [S2 * DI];
__device__ float g_ph  [S_TOK * 2*DM];

#define MMA_F16(C, Ar, Br) \
    asm volatile( \
        "mma.sync.aligned.m16n8k16.row.col.f32.f16.f16.f32 " \
        "{%0,%1,%2,%3}, {%4,%5,%6,%7}, {%8,%9}, {%0,%1,%2,%3};" \
        : "+f"(C[0]), "+f"(C[1]), "+f"(C[2]), "+f"(C[3]) \
        : "r"(Ar[0]), "r"(Ar[1]), "r"(Ar[2]), "r"(Ar[3]), \
          "r"(Br[0]), "r"(Br[1]))

// fp16 hi/lo split of fp32 pair (drop lo*lo term ~2^-22)
__device__ __forceinline__ void f16split2(float x, float y, unsigned& hi2, unsigned& lo2) {
    __half hx = __float2half_rn(x), hy = __float2half_rn(y);
    float rx = x - __half2float(hx), ry = y - __half2float(hy);
    __half2 h = __halves2half2(hx, hy);
    __half2 l = __halves2half2(__float2half_rn(rx), __float2half_rn(ry));
    hi2 = *(unsigned*)&h;
    lo2 = *(unsigned*)&l;
}

// ---------------- LayerNorm ------------------------------------------------
__global__ void ln_kernel(const float* __restrict__ x, const float* __restrict__ g,
                          const float* __restrict__ b, float* __restrict__ out) {
    int row = blockIdx.x;
    const float* xr = x + (size_t)row * DM;
    float* orow = out + (size_t)row * DM;
    int t = threadIdx.x;
    float v0 = xr[t], v1 = xr[t + 256], v2 = xr[t + 512];
    float s = v0 + v1 + v2;
    float ss = v0*v0 + v1*v1 + v2*v2;
    #pragma unroll
    for (int o = 16; o; o >>= 1) {
        s  += __shfl_xor_sync(0xffffffffu, s,  o);
        ss += __shfl_xor_sync(0xffffffffu, ss, o);
    }
    __shared__ float rs[8], rss[8];
    __shared__ float mean_s, rstd_s;
    int w = t >> 5;
    if ((t & 31) == 0) { rs[w] = s; rss[w] = ss; }
    __syncthreads();
    if (t == 0) {
        float S = 0.f, SS = 0.f;
        #pragma unroll
        for (int i = 0; i < 8; i++) { S += rs[i]; SS += rss[i]; }
        float m = S * (1.0f / 768.0f);
        float var = SS * (1.0f / 768.0f) - m * m;
        mean_s = m;
        rstd_s = rsqrtf(var + 1e-5f);
    }
    __syncthreads();
    float m = mean_s, r = rstd_s;
    orow[t]       = (v0 - m) * r * g[t]       + b[t];
    orow[t + 256] = (v1 - m) * r * g[t + 256] + b[t + 256];
    orow[t + 512] = (v2 - m) * r * g[t + 512] + b[t + 512];
}

// ============ BIG-TILE 3xFP16 GEMM (known-good R16) ========================
#define GBM 128
#define GBN 128
#define GBK 16
#define FAS 12
#define FBS 136
#define FASZ (GBM * FAS)
#define FBSZ (8 * FBS)

__global__ void __launch_bounds__(128, 3)
gemm_big_kernel(const float* __restrict__ A, const float* __restrict__ B,
                const float* __restrict__ bias, const float* __restrict__ resid,
                float* __restrict__ C, int M, int N, int K, int act) {
    __shared__ unsigned Ah[2][FASZ], Al[2][FASZ];
    __shared__ unsigned Bh[2][FBSZ], Bl[2][FBSZ];

    const int t = threadIdx.x;
    const int warp = t >> 5, lane = t & 31;
    const int g = lane >> 2, tig = lane & 3;
    const int wm = warp >> 1, wn = warp & 1;
    const int m0 = blockIdx.y * GBM, n0 = blockIdx.x * GBN;

    const int arow = t >> 2, akq = t & 3;
    const int bkp = t >> 5, bn4 = (t & 31) * 4;

    float c[4][8][4];
    #pragma unroll
    for (int mb = 0; mb < 4; mb++)
        #pragma unroll
        for (int nb = 0; nb < 8; nb++)
            #pragma unroll
            for (int r = 0; r < 4; r++) c[mb][nb][r] = 0.f;

    const int nIter = K / GBK;

    float4 ra[4], rba[2], rbb[2];
    #pragma unroll
    for (int q = 0; q < 4; q++)
        ra[q] = *(const float4*)&A[(size_t)(m0 + arow + q * 32) * K + akq * 4];
    #pragma unroll
    for (int q = 0; q < 2; q++) {
        int kp = bkp + 4 * q;
        rba[q] = *(const float4*)&B[(size_t)(2 * kp)     * N + n0 + bn4];
        rbb[q] = *(const float4*)&B[(size_t)(2 * kp + 1) * N + n0 + bn4];
    }
    {
        #pragma unroll
        for (int q = 0; q < 4; q++) {
            int base = (arow + q * 32) * FAS + akq * 2;
            unsigned h0, l0, h1, l1;
            f16split2(ra[q].x, ra[q].y, h0, l0);
            f16split2(ra[q].z, ra[q].w, h1, l1);
            *(uint2*)&Ah[0][base] = make_uint2(h0, h1);
            *(uint2*)&Al[0][base] = make_uint2(l0, l1);
        }
        #pragma unroll
        for (int q = 0; q < 2; q++) {
            int kp = bkp + 4 * q;
            const float* pa = &rba[q].x; const float* pb = &rbb[q].x;
            unsigned h[4], l[4];
            #pragma unroll
            for (int e = 0; e < 4; e++) f16split2(pa[e], pb[e], h[e], l[e]);
            int base = kp * FBS + bn4;
            *(uint4*)&Bh[0][base] = make_uint4(h[0], h[1], h[2], h[3]);
            *(uint4*)&Bl[0][base] = make_uint4(l[0], l[1], l[2], l[3]);
        }
    }
    __syncthreads();

    for (int it = 0; it < nIter; ++it) {
        const int buf = it & 1;
        if (it + 1 < nIter) {
            int k0 = (it + 1) * GBK;
            #pragma unroll
            for (int q = 0; q < 4; q++)
                ra[q] = *(const float4*)&A[(size_t)(m0 + arow + q * 32) * K + k0 + akq * 4];
            #pragma unroll
            for (int q = 0; q < 2; q++) {
                int kp = bkp + 4 * q;
                rba[q] = *(const float4*)&B[(size_t)(k0 + 2 * kp)     * N + n0 + bn4];
                rbb[q] = *(const float4*)&B[(size_t)(k0 + 2 * kp + 1) * N + n0 + bn4];
            }
        }
        const unsigned* ah_s = Ah[buf]; const unsigned* al_s = Al[buf];
        const unsigned* bh_s = Bh[buf]; const unsigned* bl_s = Bl[buf];
        {
            unsigned ah[4][4], al[4][4];
            #pragma unroll
            for (int mb = 0; mb < 4; mb++) {
                int r0 = (wm * 64 + mb * 16 + g) * FAS;
                int r1 = r0 + 8 * FAS;
                ah[mb][0] = ah_s[r0 + tig];     ah[mb][1] = ah_s[r1 + tig];
                ah[mb][2] = ah_s[r0 + tig + 4]; ah[mb][3] = ah_s[r1 + tig + 4];
                al[mb][0] = al_s[r0 + tig];     al[mb][1] = al_s[r1 + tig];
                al[mb][2] = al_s[r0 + tig + 4]; al[mb][3] = al_s[r1 + tig + 4];
            }
            #pragma unroll
            for (int nb = 0; nb < 8; nb++) {
                int col = wn * 64 + nb * 8 + g;
                unsigned bh[2], bl[2];
                bh[0] = bh_s[tig * FBS + col]; bh[1] = bh_s[(tig + 4) * FBS + col];
                bl[0] = bl_s[tig * FBS + col]; bl[1] = bl_s[(tig + 4) * FBS + col];
                #pragma unroll
                for (int mb = 0; mb < 4; mb++) MMA_F16(c[mb][nb], al[mb], bh);
                #pragma unroll
                for (int mb = 0; mb < 4; mb++) MMA_F16(c[mb][nb], ah[mb], bl);
                #pragma unroll
                for (int mb = 0; mb < 4; mb++) MMA_F16(c[mb][nb], ah[mb], bh);
            }
        }
        if (it + 1 < nIter) {
            const int b2 = buf ^ 1;
            #pragma unroll
            for (int q = 0; q < 4; q++) {
                int base = (arow + q * 32) * FAS + akq * 2;
                unsigned h0, l0, h1, l1;
                f16split2(ra[q].x, ra[q].y, h0, l0);
                f16split2(ra[q].z, ra[q].w, h1, l1);
                *(uint2*)&Ah[b2][base] = make_uint2(h0, h1);
                *(uint2*)&Al[b2][base] = make_uint2(l0, l1);
            }
            #pragma unroll
            for (int q = 0; q < 2; q++) {
                int kp = bkp + 4 * q;
                const float* pa = &rba[q].x; const float* pb = &rbb[q].x;
                unsigned h[4], l[4];
                #pragma unroll
                for (int e = 0; e < 4; e++) f16split2(pa[e], pb[e], h[e], l[e]);
                int base = kp * FBS + bn4;
                *(uint4*)&Bh[b2][base] = make_uint4(h[0], h[1], h[2], h[3]);
                *(uint4*)&Bl[b2][base] = make_uint4(l[0], l[1], l[2], l[3]);
            }
        }
        __syncthreads();
    }

    #pragma unroll
    for (int mb = 0; mb < 4; mb++) {
        int r0 = m0 + wm * 64 + mb * 16 + g;
        #pragma unroll
        for (int nb = 0; nb < 8; nb++) {
            int col = n0 + wn * 64 + nb * 8 + tig * 2;
            float b0 = bias[col], b1 = bias[col + 1];
            #pragma unroll
            for (int half = 0; half < 2; half++) {
                int row = r0 + half * 8;
                float v0 = c[mb][nb][half * 2 + 0] + b0;
                float v1 = c[mb][nb][half * 2 + 1] + b1;
                if (act == 1) {
                    v0 = 0.5f * v0 * (1.0f + erff(v0 * 0.70710678118654752440f));
                    v1 = 0.5f * v1 * (1.0f + erff(v1 * 0.70710678118654752440f));
                }
                if (resid) {
                    const float2 rr = *(const float2*)&resid[(size_t)row * N + col];
                    v0 += rr.x; v1 += rr.y;
                }
                float2 o; o.x = v0; o.y = v1;
                *(float2*)&C[(size_t)row * N + col] = o;
            }
        }
    }
}

// ---------------- Multiend block attention (fp16 3-term MMA) ---------------
// smem words: Qh[64*36] Ql | KVh[32*72] KVl | s_s[64*68] fp32 | stats 192
#define AQH 0
#define AQL 2304
#define AKVH 4608
#define AKVL 6912
#define ASS 9216
#define ASTATS 13568
#define ATT_SMEM_FLOATS (ASTATS + 192)         // 13760
#define ATT_SMEM_BYTES (ATT_SMEM_FLOATS * 4)   // 55040

__global__ void __launch_bounds__(256)
attn_kernel(const float* __restrict__ qkv0, const float* __restrict__ qkv1,
            float* __restrict__ attm0, float* __restrict__ attm1) {
    extern __shared__ float sm[];
    unsigned* q_hi  = (unsigned*)(sm + AQH);
    unsigned* q_lo  = (unsigned*)(sm + AQL);
    unsigned* kv_hi = (unsigned*)(sm + AKVH);
    unsigned* kv_lo = (unsigned*)(sm + AKVL);
    float* s_s   = sm + ASS;
    float* m_s   = sm + ASTATS;
    float* l_s   = m_s + 64;
    float* al_s  = l_s + 64;

    const int i = blockIdx.x, h = blockIdx.y;
    const int e = blockIdx.z >> 1, b = blockIdx.z & 1;
    const float* qkvE = e ? qkv1 : qkv0;
    float* attm = e ? attm1 : attm0;
    const int t = threadIdx.x;
    const int warp = t >> 5, lane = t & 31;
    const int g = lane >> 2, tig = lane & 3;
    const int wm = warp & 3, wn = warp >> 2;
    const int qrow0 = (b * NB + i) * BSZ;
    const int ar = wm * 16;
    const int nb0 = wn * 32;

    // Q load (scaled by 1/8, exact) -> fp16 hi/lo, stride 36 words
    for (int idx = t; idx < 1024; idx += 256) {
        int qi = idx >> 4, d = (idx & 15) * 4;
        float4 v = *(const float4*)&qkvE[(size_t)(qrow0 + qi) * QKV_N + DM + h * 64 + d];
        v.x *= 0.125f; v.y *= 0.125f; v.z *= 0.125f; v.w *= 0.125f;
        unsigned h0, l0, h1, l1;
        f16split2(v.x, v.y, h0, l0);
        f16split2(v.z, v.w, h1, l1);
        int base = qi * 36 + (d >> 1);
        *(uint2*)&q_hi[base] = make_uint2(h0, h1);
        *(uint2*)&q_lo[base] = make_uint2(l0, l1);
    }
    if (t < 64) { m_s[t] = -1e30f; l_s[t] = 0.f; }
    float acc[4][4] = {};

    for (int j = 0; j <= i; ++j) {
        const float* kvb = (j < i) ? qkv0 : qkvE;
        const int krow0 = (b * NB + j) * BSZ;
        __syncthreads();
        // K tile -> [kp][key] stride 72 (word = dh pair of one key)
        for (int idx = t; idx < 1024; idx += 256) {
            int key = idx >> 4, d = (idx & 15) * 4;
            float4 v = *(const float4*)&kvb[(size_t)(krow0 + key) * QKV_N + 2 * DM + h * 64 + d];
            unsigned h0, l0, h1, l1;
            f16split2(v.x, v.y, h0, l0);
            f16split2(v.z, v.w, h1, l1);
            int kp = d >> 1;
            kv_hi[kp * 72 + key] = h0; kv_hi[(kp + 1) * 72 + key] = h1;
            kv_lo[kp * 72 + key] = l0; kv_lo[(kp + 1) * 72 + key] = l1;
        }
        __syncthreads();
        // S = Q K^T  (4 k16 chunks, 3-term fp16)
        float sv[4][4] = {};
        #pragma unroll
        for (int ks = 0; ks < 4; ks++) {
            unsigned ah[4], al[4];
            int a0 = (ar + g) * 36 + 8 * ks + tig;
            int a1 = (ar + g + 8) * 36 + 8 * ks + tig;
            ah[0] = q_hi[a0]; ah[1] = q_hi[a1]; ah[2] = q_hi[a0 + 4]; ah[3] = q_hi[a1 + 4];
            al[0] = q_lo[a0]; al[1] = q_lo[a1]; al[2] = q_lo[a0 + 4]; al[3] = q_lo[a1 + 4];
            unsigned bh[4][2], bl[4][2];
            #pragma unroll
            for (int jt = 0; jt < 4; jt++) {
                int col = nb0 + jt * 8 + g;
                int b0 = (8 * ks + tig) * 72 + col;
                int b1 = (8 * ks + tig + 4) * 72 + col;
                bh[jt][0] = kv_hi[b0]; bh[jt][1] = kv_hi[b1];
                bl[jt][0] = kv_lo[b0]; bl[jt][1] = kv_lo[b1];
            }
            #pragma unroll
            for (int jt = 0; jt < 4; jt++) MMA_F16(sv[jt], al, bh[jt]);
            #pragma unroll
            for (int jt = 0; jt < 4; jt++) MMA_F16(sv[jt], ah, bl[jt]);
            #pragma unroll
            for (int jt = 0; jt < 4; jt++) MMA_F16(sv[jt], ah, bh[jt]);
        }
        #pragma unroll
        for (int jt = 0; jt < 4; jt++) {
            int col = nb0 + jt * 8 + 2 * tig;
            float2 v01; v01.x = sv[jt][0]; v01.y = sv[jt][1];
            float2 v23; v23.x = sv[jt][2]; v23.y = sv[jt][3];
            *(float2*)&s_s[(ar + g) * 68 + col]     = v01;
            *(float2*)&s_s[(ar + g + 8) * 68 + col] = v23;
        }
        __syncthreads();
        // online softmax
        {
            int q = t >> 2, p = t & 3;
            int base = q * 68 + p * 16;
            float lm = -1e30f;
            #pragma unroll
            for (int kk = 0; kk < 16; kk++) lm = fmaxf(lm, s_s[base + kk]);
            lm = fmaxf(lm, __shfl_xor_sync(0xffffffffu, lm, 1));
            lm = fmaxf(lm, __shfl_xor_sync(0xffffffffu, lm, 2));
            float mold = m_s[q];
            float mnew = fmaxf(mold, lm);
            float ls = 0.f;
            #pragma unroll
            for (int kk = 0; kk < 16; kk++) {
                float pp = __expf(s_s[base + kk] - mnew);
                s_s[base + kk] = pp;
                ls += pp;
            }
            ls += __shfl_xor_sync(0xffffffffu, ls, 1);
            ls += __shfl_xor_sync(0xffffffffu, ls, 2);
            if (p == 0) {
                float alpha = __expf(mold - mnew);
                al_s[q] = alpha;
                l_s[q] = l_s[q] * alpha + ls;
                m_s[q] = mnew;
            }
        }
        // V tile -> [keypair][dh] stride 72 (word = key pair at one dh)
        for (int idx = t; idx < 512; idx += 256) {
            int kp = idx >> 4, d = (idx & 15) * 4;
            const float* r0p = &kvb[(size_t)(krow0 + 2 * kp)     * QKV_N + h * 64 + d];
            const float* r1p = &kvb[(size_t)(krow0 + 2 * kp + 1) * QKV_N + h * 64 + d];
            float4 va = *(const float4*)r0p;
            float4 vb = *(const float4*)r1p;
            unsigned h0, l0, h1, l1, h2, l2, h3, l3;
            f16split2(va.x, vb.x, h0, l0);
            f16split2(va.y, vb.y, h1, l1);
            f16split2(va.z, vb.z, h2, l2);
            f16split2(va.w, vb.w, h3, l3);
            int base = kp * 72 + d;
            *(uint2*)&kv_hi[base]     = make_uint2(h0, h1);
            *(uint2*)&kv_hi[base + 2] = make_uint2(h2, h3);
            *(uint2*)&kv_lo[base]     = make_uint2(l0, l1);
            *(uint2*)&kv_lo[base + 2] = make_uint2(l2, l3);
        }
        __syncthreads();
        // rescale + O += P V (4 k16 chunks, split P at read)
        {
            float a0 = al_s[ar + g], a1 = al_s[ar + g + 8];
            #pragma unroll
            for (int jt = 0; jt < 4; jt++) {
                acc[jt][0] *= a0; acc[jt][1] *= a0;
                acc[jt][2] *= a1; acc[jt][3] *= a1;
            }
        }
        #pragma unroll
        for (int ks = 0; ks < 4; ks++) {
            int r0w = (ar + g) * 68 + 16 * ks + 2 * tig;
            int r1w = (ar + g + 8) * 68 + 16 * ks + 2 * tig;
            unsigned ah[4], al[4];
            f16split2(s_s[r0w],     s_s[r0w + 1], ah[0], al[0]);
            f16split2(s_s[r1w],     s_s[r1w + 1], ah[1], al[1]);
            f16split2(s_s[r0w + 8], s_s[r0w + 9], ah[2], al[2]);
            f16split2(s_s[r1w + 8], s_s[r1w + 9], ah[3], al[3]);
            unsigned bh[4][2], bl[4][2];
            #pragma unroll
            for (int jt = 0; jt < 4; jt++) {
                int col = nb0 + jt * 8 + g;
                int b0 = (8 * ks + tig) * 72 + col;
                int b1 = (8 * ks + tig + 4) * 72 + col;
                bh[jt][0] = kv_hi[b0]; bh[jt][1] = kv_hi[b1];
                bl[jt][0] = kv_lo[b0]; bl[jt][1] = kv_lo[b1];
            }
            #pragma unroll
            for (int jt = 0; jt < 4; jt++) MMA_F16(acc[jt], al, bh[jt]);
            #pragma unroll
            for (int jt = 0; jt < 4; jt++) MMA_F16(acc[jt], ah, bl[jt]);
            #pragma unroll
            for (int jt = 0; jt < 4; jt++) MMA_F16(acc[jt], ah, bh[jt]);
        }
    }
    // epilogue
    {
        const int r0 = ar + g, r1 = ar + g + 8;
        const float inv0 = 1.0f / l_s[r0], inv1 = 1.0f / l_s[r1];
        #pragma unroll
        for (int jt = 0; jt < 4; jt++) {
            int col = h * 64 + nb0 + jt * 8 + 2 * tig;
            float2 o0; o0.x = acc[jt][0] * inv0; o0.y = acc[jt][1] * inv0;
            float2 o1; o1.x = acc[jt][2] * inv1; o1.y = acc[jt][3] * inv1;
            *(float2*)&attm[(size_t)(qrow0 + r0) * DM + col] = o0;
            *(float2*)&attm[(size_t)(qrow0 + r1) * DM + col] = o1;
        }
    }
}

// ---------------- Pose projection + quaternion normalize -------------------
__global__ void pose_kernel(const float* __restrict__ ph, const float* __restrict__ w,
                            const float* __restrict__ bias, float* __restrict__ out) {
    int row = blockIdx.x;
    int t = threadIdx.x;
    const float* hr = ph + (size_t)row * (2 * DM);
    float part[7] = {};
    for (int j = t; j < 2 * DM; j += 256) {
        float hv = hr[j];
        #pragma unroll
        for (int o = 0; o < 7; o++) part[o] += hv * w[j * 7 + o];
    }
    #pragma unroll
    for (int o = 0; o < 7; o++)
        #pragma unroll
        for (int s = 16; s; s >>= 1)
            part[o] += __shfl_xor_sync(0xffffffffu, part[o], s);
    __shared__ float red[8][7];
    int wi = t >> 5;
    if ((t & 31) == 0)
        #pragma unroll
        for (int o = 0; o < 7; o++) red[wi][o] = part[o];
    __syncthreads();
    if (t == 0) {
        float hv[7];
        #pragma unroll
        for (int o = 0; o < 7; o++) {
            hv[o] = bias[o];
            for (int k = 0; k < 8; k++) hv[o] += red[k][o];
        }
        float q0 = hv[3], q1 = hv[4], q2 = hv[5], q3 = hv[6];
        float inv = rsqrtf(q0*q0 + q1*q1 + q2*q2 + q3*q3);
        q0 *= inv; q1 *= inv; q2 *= inv; q3 *= inv;
        if (q0 < 0.f) { q0 = -q0; q1 = -q1; q2 = -q2; q3 = -q3; }
        float* orow = out + (size_t)row * 7;
        orow[0] = hv[0]; orow[1] = hv[1]; orow[2] = hv[2];
        orow[3] = q0; orow[4] = q1; orow[5] = q2; orow[6] = q3;
    }
}

// ---------------------------------------------------------------------------
extern "C" void kernel_launch(void* const* d_in, const int* in_sizes, int n_in,
                              void* d_out, int out_size) {
    const float* x0        = (const float*)d_in[0];
    const float* x1        = (const float*)d_in[1];
    const float* ln1_g     = (const float*)d_in[2];
    const float* ln1_b     = (const float*)d_in[3];
    const float* attn_w    = (const float*)d_in[4];
    const float* attn_b    = (const float*)d_in[5];
    const float* proj_w    = (const float*)d_in[6];
    const float* proj_b    = (const float*)d_in[7];
    const float* ln2_g     = (const float*)d_in[8];
    const float* ln2_b     = (const float*)d_in[9];
    const float* fc_w      = (const float*)d_in[10];
    const float* fc_b      = (const float*)d_in[11];
    const float* mproj_w   = (const float*)d_in[12];
    const float* mproj_b   = (const float*)d_in[13];
    const float* pose_fc_w = (const float*)d_in[14];
    const float* pose_fc_b = (const float*)d_in[15];
    const float* pose_pw   = (const float*)d_in[16];
    const float* pose_pb   = (const float*)d_in[17];
    float* out = (float*)d_out;

    float *a, *qkv, *attmp, *xa, *hbuf, *ph;
    cudaGetSymbolAddress((void**)&a,     g_a);
    cudaGetSymbolAddress((void**)&qkv,   g_qkv);
    cudaGetSymbolAddress((void**)&attmp, g_attm);
    cudaGetSymbolAddress((void**)&xa,    g_xa);
    cudaGetSymbolAddress((void**)&hbuf,  g_h);
    cudaGetSymbolAddress((void**)&ph,    g_ph);

    const size_t OFF = (size_t)S_TOK * DM;
    cudaFuncSetAttribute(attn_kernel, cudaFuncAttributeMaxDynamicSharedMemorySize,
                         ATT_SMEM_BYTES);

    ln_kernel<<<S_TOK, 256>>>(x0, ln1_g, ln1_b, a);
    ln_kernel<<<S_TOK, 256>>>(x1, ln1_g, ln1_b, a + OFF);
    gemm_big_kernel<<<dim3(QKV_N / GBN, S2 / GBM), 128>>>(
        a, attn_w, attn_b, nullptr, qkv, S2, QKV_N, DM, 0);
    attn_kernel<<<dim3(NB, NH, 4), 256, ATT_SMEM_BYTES>>>(
        qkv, qkv + (size_t)S_TOK * QKV_N, attmp, attmp + OFF);
    gemm_big_kernel<<<dim3(DM / GBN, S_TOK / GBM), 128>>>(
        attmp, proj_w, proj_b, x0, xa, S_TOK, DM, DM, 0);
    gemm_big_kernel<<<dim3(DM / GBN, S_TOK / GBM), 128>>>(
        attmp + OFF, proj_w, proj_b, x1, xa + OFF, S_TOK, DM, DM, 0);
    ln_kernel<<<S2, 256>>>(xa, ln2_g, ln2_b, a);
    gemm_big_kernel<<<dim3(DI / GBN, S2 / GBM), 128>>>(
        a, fc_w, fc_b, nullptr, hbuf, S2, DI, DM, 1);
    gemm_big_kernel<<<dim3(DM / GBN, S2 / GBM), 128>>>(
        hbuf, mproj_w, mproj_b, xa, out, S2, DM, DI, 0);
    gemm_big_kernel<<<dim3((2 * DM) / GBN, S_TOK / GBM), 128>>>(
        out + OFF, pose_fc_w, pose_fc_b, nullptr, ph, S_TOK, 2 * DM, DM, 1);
    pose_kernel<<<S_TOK, 256>>>(ph, pose_pw, pose_pb, out + 2 * OFF);
}